// round 9
// baseline (speedup 1.0000x reference)
#include <cuda_runtime.h>
#include <stdint.h>

#define N_VOX        200000
#define N_COLS       5
#define N_CLUSTS     1024
#define PTS_PER      128
#define N_EDGES      8192
#define NCTA         1216          // 152 SMs x 8 CTAs: exactly one wave
#define BLK_BYTES    4608
#define S1_BYTES     3072          // xy (2048) + z (1024)
#define S2_BYTES     1536          // nx/ny/nz (3 x 512)

typedef unsigned long long ull;

// One contiguous packed block per cluster -> tiles load as 2 bulk copies.
struct __align__(16) ClustBlk {
    ulonglong2 xy[PTS_PER];        // (xdup, ydup) f32x2 packs       [0, 2048)
    ull        z[PTS_PER];         // zdup                           [2048, 3072)
    ull        nx[64];             // (-x[2k], -x[2k+1])             [3072, 3584)
    ull        ny[64];             //                                [3584, 4096)
    ull        nz[64];             //                                [4096, 4608)
};
__device__ ClustBlk g_blk[N_CLUSTS];

// ---- packed f32x2 helpers (sm_103a FFMA2 path, PTX-only) ----
__device__ __forceinline__ ull pack2(float lo, float hi) {
    ull r; asm("mov.b64 %0, {%1,%2};" : "=l"(r) : "f"(lo), "f"(hi)); return r;
}
__device__ __forceinline__ void unpack2(ull v, float& lo, float& hi) {
    asm("mov.b64 {%0,%1}, %2;" : "=f"(lo), "=f"(hi) : "l"(v));
}
__device__ __forceinline__ ull add2(ull a, ull b) {
    ull r; asm("add.rn.f32x2 %0, %1, %2;" : "=l"(r) : "l"(a), "l"(b)); return r;
}
__device__ __forceinline__ ull mul2(ull a, ull b) {
    ull r; asm("mul.rn.f32x2 %0, %1, %2;" : "=l"(r) : "l"(a), "l"(b)); return r;
}
__device__ __forceinline__ ull fma2(ull a, ull b, ull c) {
    ull r; asm("fma.rn.f32x2 %0, %1, %2, %3;" : "=l"(r) : "l"(a), "l"(b), "l"(c)); return r;
}

// ---- async-copy / mbarrier helpers ----
__device__ __forceinline__ uint32_t smem_u32(const void* p) {
    return (uint32_t)__cvta_generic_to_shared(p);
}
__device__ __forceinline__ void bulk_g2s(uint32_t dst, const void* src, int bytes, uint32_t mbar) {
    asm volatile(
        "cp.async.bulk.shared::cluster.global.mbarrier::complete_tx::bytes [%0], [%1], %2, [%3];"
        :: "r"(dst), "l"(src), "r"(bytes), "r"(mbar) : "memory");
}
__device__ __forceinline__ void mbar_init(uint32_t mbar, unsigned cnt) {
    asm volatile("mbarrier.init.shared.b64 [%0], %1;" :: "r"(mbar), "r"(cnt) : "memory");
}
__device__ __forceinline__ void mbar_expect(uint32_t mbar, unsigned bytes) {
    asm volatile("mbarrier.arrive.expect_tx.shared.b64 _, [%0], %1;"
                 :: "r"(mbar), "r"(bytes) : "memory");
}
__device__ __forceinline__ void mbar_wait(uint32_t mbar, unsigned parity) {
    asm volatile(
        "{\n\t.reg .pred P;\n\t"
        "WLP_%=:\n\t"
        "mbarrier.try_wait.parity.acquire.cta.shared::cta.b64 P, [%0], %1, 0x989680;\n\t"
        "@P bra.uni WDN_%=;\n\t"
        "bra.uni WLP_%=;\n\t"
        "WDN_%=:\n\t}"
        :: "r"(mbar), "r"(parity) : "memory");
}
__device__ __forceinline__ void fence_pa() {
    asm volatile("fence.proxy.async.shared::cta;" ::: "memory");
}

// -------------------------------------------------------------------------
// Kernel 1: gather + pre-pack into per-cluster contiguous blocks.
// -------------------------------------------------------------------------
__global__ void gather_pts_kernel(const float* __restrict__ data,
                                  const int* __restrict__ clusts) {
    int i = blockIdx.x * blockDim.x + threadIdx.x;
    if (i >= N_CLUSTS * PTS_PER) return;
    int c = i >> 7, p = i & 127;
    int idx = clusts[i];
    const float* q = data + (size_t)idx * N_COLS + 1;
    float x = q[0], y = q[1], z = q[2];

    g_blk[c].xy[p] = make_ulonglong2(pack2(x, x), pack2(y, y));
    g_blk[c].z[p]  = pack2(z, z);

    float mx = -x, my = -y, mz = -z;
    float ox = __shfl_down_sync(0xFFFFFFFFu, mx, 1);
    float oy = __shfl_down_sync(0xFFFFFFFFu, my, 1);
    float oz = __shfl_down_sync(0xFFFFFFFFu, mz, 1);
    if ((p & 1) == 0) {
        int k = p >> 1;
        g_blk[c].nx[k] = pack2(mx, ox);
        g_blk[c].ny[k] = pack2(my, oy);
        g_blk[c].nz[k] = pack2(mz, oz);
    }
}

// -------------------------------------------------------------------------
// Kernel 2: persistent CTAs (one wave), double-buffered async tile loads.
// Edge k of CTA b is e = b + k*NCTA. Thread (ti,tj): ti=t>>4 owns i1 rows
// [16*ti,16*ti+16); tj=t&15 owns i2 packs k = tj+16*b.
// -------------------------------------------------------------------------
__global__ __launch_bounds__(128, 8)
void edge_feats_kernel(const int* __restrict__ edge_index,
                       float* __restrict__ out) {
    __shared__ __align__(16) char sbuf[2][BLK_BYTES];
    __shared__ ull s_best;
    __shared__ ull s_mbar[2];

    const int t   = threadIdx.x;
    const int bid = blockIdx.x;
    const int nk  = (N_EDGES - bid + NCTA - 1) / NCTA;

    const uint32_t mb0   = smem_u32(&s_mbar[0]);
    const uint32_t mb1   = smem_u32(&s_mbar[1]);
    const uint32_t buf_a = smem_u32(&sbuf[0][0]);

    if (t == 0) {
        s_best = ~0ull;
        mbar_init(mb0, 1);
        mbar_init(mb1, 1);
    }
    __syncthreads();

    // Kick off edge 0 into buffer 0.
    if (t == 0) {
        int c1 = edge_index[bid];
        int c2 = edge_index[N_EDGES + bid];
        mbar_expect(mb0, BLK_BYTES);
        bulk_g2s(buf_a, (const char*)g_blk + (size_t)c1 * BLK_BYTES, S1_BYTES, mb0);
        bulk_g2s(buf_a + S1_BYTES,
                 (const char*)g_blk + (size_t)c2 * BLK_BYTES + S1_BYTES, S2_BYTES, mb0);
    }

    const int ti = t >> 4;
    const int tj = t & 15;
    const int i1base = ti * 16;
    unsigned ph[2] = {0u, 0u};     // per-buffer phase parity (tracked by every thread)

    for (int k = 0; k < nk; k++) {
        const int e   = bid + k * NCTA;
        const int buf = k & 1;

        // Issue NEXT edge's tiles into the other buffer (its own mbarrier).
        if (t == 0 && k + 1 < nk) {
            int en = bid + (k + 1) * NCTA;
            int c1 = edge_index[en];
            int c2 = edge_index[N_EDGES + en];
            uint32_t mbn = (buf ? mb0 : mb1);
            uint32_t d   = buf_a + (buf ^ 1) * BLK_BYTES;
            fence_pa();
            mbar_expect(mbn, BLK_BYTES);
            bulk_g2s(d, (const char*)g_blk + (size_t)c1 * BLK_BYTES, S1_BYTES, mbn);
            bulk_g2s(d + S1_BYTES,
                     (const char*)g_blk + (size_t)c2 * BLK_BYTES + S1_BYTES, S2_BYTES, mbn);
        }

        // Wait for THIS edge's tiles.
        mbar_wait(buf ? mb1 : mb0, ph[buf]);
        ph[buf] ^= 1u;

        const ulonglong2* s1xy = (const ulonglong2*)(sbuf[buf]);
        const ull* s1z = (const ull*)(sbuf[buf] + 2048);
        const ull* s2x = (const ull*)(sbuf[buf] + 3072);
        const ull* s2y = (const ull*)(sbuf[buf] + 3584);
        const ull* s2z = (const ull*)(sbuf[buf] + 4096);

        // Hoist this thread's 4 negated-v2 packs.
        ull vx[4], vy[4], vz[4];
#pragma unroll
        for (int b = 0; b < 4; b++) {
            vx[b] = s2x[tj + 16 * b];
            vy[b] = s2y[tj + 16 * b];
            vz[b] = s2z[tj + 16 * b];
        }

        float bd = __int_as_float(0x7F800000);   // +inf
        int besta = 0;

        // ---- hot loop: 16 rows; packed distances + scalar min tree ----
#pragma unroll
        for (int a = 0; a < 16; a++) {
            ulonglong2 pxy = s1xy[i1base + a];
            ull pz = s1z[i1base + a];

            float h[8];
#pragma unroll
            for (int b = 0; b < 4; b++) {
                ull dx = add2(pxy.x, vx[b]);
                ull dy = add2(pxy.y, vy[b]);
                ull dz = add2(pz,    vz[b]);
                ull d2 = fma2(dz, dz, fma2(dy, dy, mul2(dx, dx)));
                unpack2(d2, h[2 * b], h[2 * b + 1]);
            }

            float m01 = fminf(h[0], h[1]);
            float m23 = fminf(h[2], h[3]);
            float m45 = fminf(h[4], h[5]);
            float m67 = fminf(h[6], h[7]);
            float m = fminf(fminf(m01, m23), fminf(m45, m67));

            bool imp = (m < bd);           // last strict improvement == first
            bd = imp ? m : bd;             // row attaining the final min
            besta = imp ? a : besta;
        }

        // ---- one-shot index recovery: recompute row `besta` (identical math) ----
        {
            ulonglong2 pxy = s1xy[i1base + besta];
            ull pz = s1z[i1base + besta];

            float h[8];
#pragma unroll
            for (int b = 0; b < 4; b++) {
                ull dx = add2(pxy.x, vx[b]);
                ull dy = add2(pxy.y, vy[b]);
                ull dz = add2(pz,    vz[b]);
                ull d2 = fma2(dz, dz, fma2(dy, dy, mul2(dx, dx)));
                unpack2(d2, h[2 * b], h[2 * b + 1]);
            }

            float cur = __int_as_float(0x7F800000);
            int bidx = 0;
            const int rowbase = (i1base + besta) * PTS_PER + 2 * tj;
#pragma unroll
            for (int q = 0; q < 8; q++) {
                int flat = rowbase + 32 * (q >> 1) + (q & 1);
                if (h[q] < cur) { cur = h[q]; bidx = flat; }   // ascending flat, strict <
            }

            ull key = ((ull)__float_as_uint(cur) << 32) | (unsigned int)bidx;
#pragma unroll
            for (int off = 16; off > 0; off >>= 1) {
                ull o = __shfl_down_sync(0xFFFFFFFFu, key, off);
                key = (o < key) ? o : key;
            }
            if ((t & 31) == 0) atomicMin(&s_best, key);
        }
        __syncthreads();

        // ---- epilogue: t0 writes row 2e, t1 writes row 2e+1 ----
        if (t < 2) {
            ull kb = s_best;
            int f  = (int)(kb & 0xFFFFFFFFu);
            int w1 = f >> 7;
            int w2 = f & 127;

            float v1x, v1y, v1z, tmp;
            ulonglong2 pxy = s1xy[w1];
            unpack2(pxy.x, v1x, tmp);
            unpack2(pxy.y, v1y, tmp);
            unpack2(s1z[w1], v1z, tmp);

            int kk = w2 >> 1, half = w2 & 1;
            float lox, hix, loy, hiy, loz, hiz;
            unpack2(s2x[kk], lox, hix);
            unpack2(s2y[kk], loy, hiy);
            unpack2(s2z[kk], loz, hiz);
            float v2x = -(half ? hix : lox);
            float v2y = -(half ? hiy : loy);
            float v2z = -(half ? hiz : loz);

            float dx = v1x - v2x;
            float dy = v1y - v2y;
            float dz = v1z - v2z;
            float lend = sqrtf(fmaf(dz, dz, fmaf(dy, dy, dx * dx)));
            float nx, ny, nz;
            if (lend > 0.0f) {
                nx = dx / lend; ny = dy / lend; nz = dz / lend;
            } else {
                nx = dx; ny = dy; nz = dz;
            }

            float B[9];
            B[0] = nx * nx; B[1] = nx * ny; B[2] = nx * nz;
            B[3] = ny * nx; B[4] = ny * ny; B[5] = ny * nz;
            B[6] = nz * nx; B[7] = nz * ny; B[8] = nz * nz;

            float ax, ay, az, bx, by, bz, sg;
            if (t == 0) { ax = v1x; ay = v1y; az = v1z; bx = v2x; by = v2y; bz = v2z; sg = 1.0f; }
            else        { ax = v2x; ay = v2y; az = v2z; bx = v1x; by = v1y; bz = v1z; sg = -1.0f; }

            float* o = out + (size_t)(2 * e + t) * 19;
            o[0] = ax; o[1] = ay; o[2] = az;
            o[3] = bx; o[4] = by; o[5] = bz;
            o[6] = sg * nx; o[7] = sg * ny; o[8] = sg * nz;
            o[9] = lend;
#pragma unroll
            for (int q = 0; q < 9; q++) o[10 + q] = B[q];
        }
        if (t == 0) s_best = ~0ull;
        __syncthreads();
    }
}

// -------------------------------------------------------------------------
extern "C" void kernel_launch(void* const* d_in, const int* in_sizes, int n_in,
                              void* d_out, int out_size) {
    const float* data       = (const float*)d_in[0];   // [200000, 5] f32
    const int*   clusts     = (const int*)d_in[1];     // [1024, 128] i32
    const int*   edge_index = (const int*)d_in[2];     // [2, 8192] i32
    float*       out        = (float*)d_out;           // [16384, 19] f32

    gather_pts_kernel<<<(N_CLUSTS * PTS_PER + 255) / 256, 256>>>(data, clusts);
    edge_feats_kernel<<<NCTA, 128>>>(edge_index, out);
}

// round 10
// speedup vs baseline: 1.0654x; 1.0654x over previous
#include <cuda_runtime.h>
#include <stdint.h>

#define N_VOX        200000
#define N_COLS       5
#define N_CLUSTS     1024
#define PTS_PER      128
#define N_EDGES      8192
#define BLK_BYTES    4608
#define S1_BYTES     3072     // xy (2048) + z (1024)

typedef unsigned long long ull;

// One contiguous packed block per cluster:
//   xy : (xdup, ydup) f32x2 packs   [0, 2048)
//   z  : zdup packs                 [2048, 3072)
//   nx : (-x[2k], -x[2k+1])         [3072, 3584)
//   ny :                            [3584, 4096)
//   nz :                            [4096, 4608)
struct __align__(16) ClustBlk {
    ulonglong2 xy[PTS_PER];
    ull        z[PTS_PER];
    ull        nx[64];
    ull        ny[64];
    ull        nz[64];
};
__device__ ClustBlk g_blk[N_CLUSTS];

// ---- packed f32x2 helpers (sm_103a FFMA2 path, PTX-only) ----
__device__ __forceinline__ ull pack2(float lo, float hi) {
    ull r; asm("mov.b64 %0, {%1,%2};" : "=l"(r) : "f"(lo), "f"(hi)); return r;
}
__device__ __forceinline__ void unpack2(ull v, float& lo, float& hi) {
    asm("mov.b64 {%0,%1}, %2;" : "=f"(lo), "=f"(hi) : "l"(v));
}
__device__ __forceinline__ ull add2(ull a, ull b) {
    ull r; asm("add.rn.f32x2 %0, %1, %2;" : "=l"(r) : "l"(a), "l"(b)); return r;
}
__device__ __forceinline__ ull mul2(ull a, ull b) {
    ull r; asm("mul.rn.f32x2 %0, %1, %2;" : "=l"(r) : "l"(a), "l"(b)); return r;
}
__device__ __forceinline__ ull fma2(ull a, ull b, ull c) {
    ull r; asm("fma.rn.f32x2 %0, %1, %2, %3;" : "=l"(r) : "l"(a), "l"(b), "l"(c)); return r;
}

// -------------------------------------------------------------------------
// Kernel 1: gather + pre-pack into per-cluster contiguous blocks.
// -------------------------------------------------------------------------
__global__ void gather_pts_kernel(const float* __restrict__ data,
                                  const int* __restrict__ clusts) {
    int i = blockIdx.x * blockDim.x + threadIdx.x;
    if (i >= N_CLUSTS * PTS_PER) return;
    int c = i >> 7, p = i & 127;
    int idx = clusts[i];
    const float* q = data + (size_t)idx * N_COLS + 1;
    float x = q[0], y = q[1], z = q[2];

    g_blk[c].xy[p] = make_ulonglong2(pack2(x, x), pack2(y, y));
    g_blk[c].z[p]  = pack2(z, z);

    float mx = -x, my = -y, mz = -z;
    float ox = __shfl_down_sync(0xFFFFFFFFu, mx, 1);
    float oy = __shfl_down_sync(0xFFFFFFFFu, my, 1);
    float oz = __shfl_down_sync(0xFFFFFFFFu, mz, 1);
    if ((p & 1) == 0) {
        int k = p >> 1;
        g_blk[c].nx[k] = pack2(mx, ox);
        g_blk[c].ny[k] = pack2(my, oy);
        g_blk[c].nz[k] = pack2(mz, oz);
    }
}

// -------------------------------------------------------------------------
// Kernel 2: one CTA (128 threads) per edge (R6 schedule).
// Thread (ti, tj): ti = t>>4 owns i1 rows [16*ti, 16*ti+16);
//                  tj = t&15 owns i2 packs k = tj + 16*b (b=0..3).
// sbuf[0,3072)   = c1 xy+z   (from g_blk[c1] bytes [0,3072))
// sbuf[3072,4608)= c2 nx/ny/nz (from g_blk[c2] bytes [3072,4608))
// -------------------------------------------------------------------------
__global__ __launch_bounds__(128, 8)
void edge_feats_kernel(const int* __restrict__ edge_index,
                       float* __restrict__ out) {
    __shared__ __align__(16) char sbuf[BLK_BYTES];
    __shared__ ull s_best;

    const int e = blockIdx.x;
    const int t = threadIdx.x;

    const int c1 = edge_index[e];
    const int c2 = edge_index[N_EDGES + e];

    if (t == 0) s_best = ~0ull;

    // Prologue: 288 16B chunks; src block switches at chunk 192 (byte 3072).
    {
        const char* b1 = (const char*)&g_blk[c1];
        const char* b2 = (const char*)&g_blk[c2];
#pragma unroll
        for (int r = 0; r < 3; r++) {
            int c = t + r * 128;
            if (r < 2 || t < 32) {            // c < 288
                const char* src = (c < 192) ? b1 : b2;
                uint4 v = *(const uint4*)(src + c * 16);
                *(uint4*)(sbuf + c * 16) = v;
            }
        }
    }
    __syncthreads();

    const ulonglong2* s1xy = (const ulonglong2*)(sbuf);
    const ull* s1z = (const ull*)(sbuf + 2048);
    const ull* s2x = (const ull*)(sbuf + 3072);
    const ull* s2y = (const ull*)(sbuf + 3584);
    const ull* s2z = (const ull*)(sbuf + 4096);

    const int ti = t >> 4;
    const int tj = t & 15;
    const int i1base = ti * 16;

    // Hoist this thread's 4 negated-v2 packs (conflict-free LDS.64).
    ull vx[4], vy[4], vz[4];
#pragma unroll
    for (int b = 0; b < 4; b++) {
        vx[b] = s2x[tj + 16 * b];
        vy[b] = s2y[tj + 16 * b];
        vz[b] = s2z[tj + 16 * b];
    }

    float bd = __int_as_float(0x7F800000);   // +inf
    int besta = 0;

    // ---- hot loop: 16 rows; packed distances + scalar min tree ----
#pragma unroll
    for (int a = 0; a < 16; a++) {
        ulonglong2 pxy = s1xy[i1base + a];
        ull pz = s1z[i1base + a];

        float h[8];
#pragma unroll
        for (int b = 0; b < 4; b++) {
            ull dx = add2(pxy.x, vx[b]);
            ull dy = add2(pxy.y, vy[b]);
            ull dz = add2(pz,    vz[b]);
            ull d2 = fma2(dz, dz, fma2(dy, dy, mul2(dx, dx)));
            unpack2(d2, h[2 * b], h[2 * b + 1]);
        }

        float m01 = fminf(h[0], h[1]);
        float m23 = fminf(h[2], h[3]);
        float m45 = fminf(h[4], h[5]);
        float m67 = fminf(h[6], h[7]);
        float m = fminf(fminf(m01, m23), fminf(m45, m67));

        bool imp = (m < bd);           // last strict improvement == first
        bd = imp ? m : bd;             // row attaining the final min
        besta = imp ? a : besta;
    }

    // ---- one-shot index recovery: recompute row `besta` (identical math) ----
    {
        ulonglong2 pxy = s1xy[i1base + besta];
        ull pz = s1z[i1base + besta];

        float h[8];
#pragma unroll
        for (int b = 0; b < 4; b++) {
            ull dx = add2(pxy.x, vx[b]);
            ull dy = add2(pxy.y, vy[b]);
            ull dz = add2(pz,    vz[b]);
            ull d2 = fma2(dz, dz, fma2(dy, dy, mul2(dx, dx)));
            unpack2(d2, h[2 * b], h[2 * b + 1]);
        }

        float cur = __int_as_float(0x7F800000);
        int bidx = 0;
        const int rowbase = (i1base + besta) * PTS_PER + 2 * tj;
#pragma unroll
        for (int q = 0; q < 8; q++) {
            int flat = rowbase + 32 * (q >> 1) + (q & 1);
            if (h[q] < cur) { cur = h[q]; bidx = flat; }   // ascending flat, strict <
        }

        // Pack (d2, flat): uint64 min == lexicographic min (d2 >= 0).
        ull key = ((ull)__float_as_uint(cur) << 32) | (unsigned int)bidx;

#pragma unroll
        for (int off = 16; off > 0; off >>= 1) {
            ull o = __shfl_down_sync(0xFFFFFFFFu, key, off);
            key = (o < key) ? o : key;
        }
        if ((t & 31) == 0) atomicMin(&s_best, key);
    }
    __syncthreads();

    // ---- epilogue: t0 writes row 2e, t1 writes row 2e+1 ----
    if (t < 2) {
        ull kb = s_best;
        int f  = (int)(kb & 0xFFFFFFFFu);
        int w1 = f >> 7;
        int w2 = f & 127;

        float v1x, v1y, v1z, tmp;
        ulonglong2 pxy = s1xy[w1];
        unpack2(pxy.x, v1x, tmp);
        unpack2(pxy.y, v1y, tmp);
        unpack2(s1z[w1], v1z, tmp);

        int kk = w2 >> 1, half = w2 & 1;
        float lox, hix, loy, hiy, loz, hiz;
        unpack2(s2x[kk], lox, hix);
        unpack2(s2y[kk], loy, hiy);
        unpack2(s2z[kk], loz, hiz);
        float v2x = -(half ? hix : lox);
        float v2y = -(half ? hiy : loy);
        float v2z = -(half ? hiz : loz);

        float dx = v1x - v2x;
        float dy = v1y - v2y;
        float dz = v1z - v2z;
        float lend = sqrtf(fmaf(dz, dz, fmaf(dy, dy, dx * dx)));
        float nx, ny, nz;
        if (lend > 0.0f) {
            nx = dx / lend; ny = dy / lend; nz = dz / lend;
        } else {
            nx = dx; ny = dy; nz = dz;
        }

        float B[9];
        B[0] = nx * nx; B[1] = nx * ny; B[2] = nx * nz;
        B[3] = ny * nx; B[4] = ny * ny; B[5] = ny * nz;
        B[6] = nz * nx; B[7] = nz * ny; B[8] = nz * nz;

        float ax, ay, az, bx, by, bz, sg;
        if (t == 0) { ax = v1x; ay = v1y; az = v1z; bx = v2x; by = v2y; bz = v2z; sg = 1.0f; }
        else        { ax = v2x; ay = v2y; az = v2z; bx = v1x; by = v1y; bz = v1z; sg = -1.0f; }

        float* o = out + (size_t)(2 * e + t) * 19;
        o[0] = ax; o[1] = ay; o[2] = az;
        o[3] = bx; o[4] = by; o[5] = bz;
        o[6] = sg * nx; o[7] = sg * ny; o[8] = sg * nz;
        o[9] = lend;
#pragma unroll
        for (int q = 0; q < 9; q++) o[10 + q] = B[q];
    }
}

// -------------------------------------------------------------------------
extern "C" void kernel_launch(void* const* d_in, const int* in_sizes, int n_in,
                              void* d_out, int out_size) {
    const float* data       = (const float*)d_in[0];   // [200000, 5] f32
    const int*   clusts     = (const int*)d_in[1];     // [1024, 128] i32
    const int*   edge_index = (const int*)d_in[2];     // [2, 8192] i32
    float*       out        = (float*)d_out;           // [16384, 19] f32

    gather_pts_kernel<<<(N_CLUSTS * PTS_PER + 255) / 256, 256>>>(data, clusts);
    edge_feats_kernel<<<N_EDGES, 128>>>(edge_index, out);
}

// round 13
// speedup vs baseline: 1.0903x; 1.0234x over previous
#include <cuda_runtime.h>
#include <stdint.h>

#define N_VOX        200000
#define N_COLS       5
#define N_CLUSTS     1024
#define PTS_PER      128
#define N_EDGES      8192
#define BLK_BYTES    4608
#define S1_BYTES     3072     // xy (2048) + z (1024)

typedef unsigned long long ull;

// One contiguous packed block per cluster:
//   xy : (xdup, ydup) f32x2 packs   [0, 2048)
//   z  : zdup packs                 [2048, 3072)
//   nx : (-x[2k], -x[2k+1])         [3072, 3584)
//   ny :                            [3584, 4096)
//   nz :                            [4096, 4608)
struct __align__(16) ClustBlk {
    ulonglong2 xy[PTS_PER];
    ull        z[PTS_PER];
    ull        nx[64];
    ull        ny[64];
    ull        nz[64];
};
__device__ ClustBlk g_blk[N_CLUSTS];

// ---- packed f32x2 helpers (sm_103a FFMA2 path, PTX-only) ----
__device__ __forceinline__ ull pack2(float lo, float hi) {
    ull r; asm("mov.b64 %0, {%1,%2};" : "=l"(r) : "f"(lo), "f"(hi)); return r;
}
__device__ __forceinline__ void unpack2(ull v, float& lo, float& hi) {
    asm("mov.b64 {%0,%1}, %2;" : "=f"(lo), "=f"(hi) : "l"(v));
}
__device__ __forceinline__ ull add2(ull a, ull b) {
    ull r; asm("add.rn.f32x2 %0, %1, %2;" : "=l"(r) : "l"(a), "l"(b)); return r;
}
__device__ __forceinline__ ull mul2(ull a, ull b) {
    ull r; asm("mul.rn.f32x2 %0, %1, %2;" : "=l"(r) : "l"(a), "l"(b)); return r;
}
__device__ __forceinline__ ull fma2(ull a, ull b, ull c) {
    ull r; asm("fma.rn.f32x2 %0, %1, %2, %3;" : "=l"(r) : "l"(a), "l"(b), "l"(c)); return r;
}

// -------------------------------------------------------------------------
// Kernel 1: gather + pre-pack into per-cluster contiguous blocks.
// -------------------------------------------------------------------------
__global__ void gather_pts_kernel(const float* __restrict__ data,
                                  const int* __restrict__ clusts) {
    int i = blockIdx.x * blockDim.x + threadIdx.x;
    if (i >= N_CLUSTS * PTS_PER) return;
    int c = i >> 7, p = i & 127;
    int idx = clusts[i];
    const float* q = data + (size_t)idx * N_COLS + 1;
    float x = q[0], y = q[1], z = q[2];

    g_blk[c].xy[p] = make_ulonglong2(pack2(x, x), pack2(y, y));
    g_blk[c].z[p]  = pack2(z, z);

    float mx = -x, my = -y, mz = -z;
    float ox = __shfl_down_sync(0xFFFFFFFFu, mx, 1);
    float oy = __shfl_down_sync(0xFFFFFFFFu, my, 1);
    float oz = __shfl_down_sync(0xFFFFFFFFu, mz, 1);
    if ((p & 1) == 0) {
        int k = p >> 1;
        g_blk[c].nx[k] = pack2(mx, ox);
        g_blk[c].ny[k] = pack2(my, oy);
        g_blk[c].nz[k] = pack2(mz, oz);
    }
}

// -------------------------------------------------------------------------
// Kernel 2: one CTA (128 threads) per edge (R6 schedule).
// __launch_bounds__(128, 10): cap regs at ~51 so 10 CTAs/SM (40 warps,
// 62.5% occupancy) fit — R10 measured the 64-reg/8-CTA config pinned at the
// 50% register-file occupancy ceiling with issue only 58.6%.
// Thread (ti, tj): ti = t>>4 owns i1 rows [16*ti, 16*ti+16);
//                  tj = t&15 owns i2 packs k = tj + 16*b (b=0..3).
// -------------------------------------------------------------------------
__global__ __launch_bounds__(128, 10)
void edge_feats_kernel(const int* __restrict__ edge_index,
                       float* __restrict__ out) {
    __shared__ __align__(16) char sbuf[BLK_BYTES];
    __shared__ ull s_best;

    const int e = blockIdx.x;
    const int t = threadIdx.x;

    const int c1 = edge_index[e];
    const int c2 = edge_index[N_EDGES + e];

    if (t == 0) s_best = ~0ull;

    // Prologue: 288 16B chunks; src block switches at chunk 192 (byte 3072).
    {
        const char* b1 = (const char*)&g_blk[c1];
        const char* b2 = (const char*)&g_blk[c2];
#pragma unroll
        for (int r = 0; r < 3; r++) {
            int c = t + r * 128;
            if (r < 2 || t < 32) {            // c < 288
                const char* src = (c < 192) ? b1 : b2;
                uint4 v = *(const uint4*)(src + c * 16);
                *(uint4*)(sbuf + c * 16) = v;
            }
        }
    }
    __syncthreads();

    const ulonglong2* s1xy = (const ulonglong2*)(sbuf);
    const ull* s1z = (const ull*)(sbuf + 2048);
    const ull* s2x = (const ull*)(sbuf + 3072);
    const ull* s2y = (const ull*)(sbuf + 3584);
    const ull* s2z = (const ull*)(sbuf + 4096);

    const int ti = t >> 4;
    const int tj = t & 15;
    const int i1base = ti * 16;

    // Hoist this thread's 4 negated-v2 packs (conflict-free LDS.64).
    ull vx[4], vy[4], vz[4];
#pragma unroll
    for (int b = 0; b < 4; b++) {
        vx[b] = s2x[tj + 16 * b];
        vy[b] = s2y[tj + 16 * b];
        vz[b] = s2z[tj + 16 * b];
    }

    float bd = __int_as_float(0x7F800000);   // +inf
    int besta = 0;

    // ---- hot loop: 16 rows; packed distances + scalar min tree ----
#pragma unroll
    for (int a = 0; a < 16; a++) {
        ulonglong2 pxy = s1xy[i1base + a];
        ull pz = s1z[i1base + a];

        float h[8];
#pragma unroll
        for (int b = 0; b < 4; b++) {
            ull dx = add2(pxy.x, vx[b]);
            ull dy = add2(pxy.y, vy[b]);
            ull dz = add2(pz,    vz[b]);
            ull d2 = fma2(dz, dz, fma2(dy, dy, mul2(dx, dx)));
            unpack2(d2, h[2 * b], h[2 * b + 1]);
        }

        float m01 = fminf(h[0], h[1]);
        float m23 = fminf(h[2], h[3]);
        float m45 = fminf(h[4], h[5]);
        float m67 = fminf(h[6], h[7]);
        float m = fminf(fminf(m01, m23), fminf(m45, m67));

        bool imp = (m < bd);           // last strict improvement == first
        bd = imp ? m : bd;             // row attaining the final min
        besta = imp ? a : besta;
    }

    // ---- one-shot index recovery: recompute row `besta` (identical math) ----
    {
        ulonglong2 pxy = s1xy[i1base + besta];
        ull pz = s1z[i1base + besta];

        float h[8];
#pragma unroll
        for (int b = 0; b < 4; b++) {
            ull dx = add2(pxy.x, vx[b]);
            ull dy = add2(pxy.y, vy[b]);
            ull dz = add2(pz,    vz[b]);
            ull d2 = fma2(dz, dz, fma2(dy, dy, mul2(dx, dx)));
            unpack2(d2, h[2 * b], h[2 * b + 1]);
        }

        float cur = __int_as_float(0x7F800000);
        int bidx = 0;
        const int rowbase = (i1base + besta) * PTS_PER + 2 * tj;
#pragma unroll
        for (int q = 0; q < 8; q++) {
            int flat = rowbase + 32 * (q >> 1) + (q & 1);
            if (h[q] < cur) { cur = h[q]; bidx = flat; }   // ascending flat, strict <
        }

        // Pack (d2, flat): uint64 min == lexicographic min (d2 >= 0).
        ull key = ((ull)__float_as_uint(cur) << 32) | (unsigned int)bidx;

#pragma unroll
        for (int off = 16; off > 0; off >>= 1) {
            ull o = __shfl_down_sync(0xFFFFFFFFu, key, off);
            key = (o < key) ? o : key;
        }
        if ((t & 31) == 0) atomicMin(&s_best, key);
    }
    __syncthreads();

    // ---- epilogue: t0 writes row 2e, t1 writes row 2e+1 ----
    if (t < 2) {
        ull kb = s_best;
        int f  = (int)(kb & 0xFFFFFFFFu);
        int w1 = f >> 7;
        int w2 = f & 127;

        float v1x, v1y, v1z, tmp;
        ulonglong2 pxy = s1xy[w1];
        unpack2(pxy.x, v1x, tmp);
        unpack2(pxy.y, v1y, tmp);
        unpack2(s1z[w1], v1z, tmp);

        int kk = w2 >> 1, half = w2 & 1;
        float lox, hix, loy, hiy, loz, hiz;
        unpack2(s2x[kk], lox, hix);
        unpack2(s2y[kk], loy, hiy);
        unpack2(s2z[kk], loz, hiz);
        float v2x = -(half ? hix : lox);
        float v2y = -(half ? hiy : loy);
        float v2z = -(half ? hiz : loz);

        float dx = v1x - v2x;
        float dy = v1y - v2y;
        float dz = v1z - v2z;
        float lend = sqrtf(fmaf(dz, dz, fmaf(dy, dy, dx * dx)));
        float nx, ny, nz;
        if (lend > 0.0f) {
            nx = dx / lend; ny = dy / lend; nz = dz / lend;
        } else {
            nx = dx; ny = dy; nz = dz;
        }

        float B[9];
        B[0] = nx * nx; B[1] = nx * ny; B[2] = nx * nz;
        B[3] = ny * nx; B[4] = ny * ny; B[5] = ny * nz;
        B[6] = nz * nx; B[7] = nz * ny; B[8] = nz * nz;

        float ax, ay, az, bx, by, bz, sg;
        if (t == 0) { ax = v1x; ay = v1y; az = v1z; bx = v2x; by = v2y; bz = v2z; sg = 1.0f; }
        else        { ax = v2x; ay = v2y; az = v2z; bx = v1x; by = v1y; bz = v1z; sg = -1.0f; }

        float* o = out + (size_t)(2 * e + t) * 19;
        o[0] = ax; o[1] = ay; o[2] = az;
        o[3] = bx; o[4] = by; o[5] = bz;
        o[6] = sg * nx; o[7] = sg * ny; o[8] = sg * nz;
        o[9] = lend;
#pragma unroll
        for (int q = 0; q < 9; q++) o[10 + q] = B[q];
    }
}

// -------------------------------------------------------------------------
extern "C" void kernel_launch(void* const* d_in, const int* in_sizes, int n_in,
                              void* d_out, int out_size) {
    const float* data       = (const float*)d_in[0];   // [200000, 5] f32
    const int*   clusts     = (const int*)d_in[1];     // [1024, 128] i32
    const int*   edge_index = (const int*)d_in[2];     // [2, 8192] i32
    float*       out        = (float*)d_out;           // [16384, 19] f32

    gather_pts_kernel<<<(N_CLUSTS * PTS_PER + 255) / 256, 256>>>(data, clusts);
    edge_feats_kernel<<<N_EDGES, 128>>>(edge_index, out);
}